// round 1
// baseline (speedup 1.0000x reference)
#include <cuda_runtime.h>

#define NN   4096
#define HH   128
#define CAP  192   // max degree capacity; Binomial(4096,0.02) max ~= 120

// Scratch (device globals: allocation-free per harness rules)
__device__ float4 g_edge[NN * CAP];   // (j_bits, decay, wc, pad) per edge
__device__ int    g_deg[NN];
__device__ float  g_h[NN * HH];
__device__ float  g_m[NN * HH];
__device__ float  g_t[NN * HH];

// ---------------------------------------------------------------------------
// Build per-row edge list from adj (2% dense) with loop-invariant weights:
//   decay = exp(-d/3),  wc = LJ_MIX * 4*eps*((s/r)^12 - (s/r)^6) = 0.04*(i12-i6)
// One warp per row, ordered ballot compaction (deterministic).
// ---------------------------------------------------------------------------
__global__ __launch_bounds__(256) void build_edges_kernel(
    const float* __restrict__ adj, const float* __restrict__ dist)
{
    int row  = (blockIdx.x * 256 + threadIdx.x) >> 5;
    int lane = threadIdx.x & 31;
    if (row >= NN) return;
    const float* arow = adj  + (long)row * NN;
    const float* drow = dist + (long)row * NN;
    int base = 0;
    for (int c0 = 0; c0 < NN; c0 += 32) {
        float a = arow[c0 + lane];
        unsigned mask = __ballot_sync(0xffffffffu, a != 0.0f);
        if (a != 0.0f) {
            int pos = base + __popc(mask & ((1u << lane) - 1u));
            if (pos < CAP) {
                float d     = drow[c0 + lane];
                float decay = __expf(d * (-1.0f / 3.0f));
                float r     = fmaxf(d, 1e-6f);
                float inv   = 3.5f / r;
                float i2    = inv * inv;
                float i6    = i2 * i2 * i2;
                float wc    = 0.04f * (i6 * i6 - i6);
                g_edge[row * CAP + pos] =
                    make_float4(__int_as_float(c0 + lane), decay, wc, 0.0f);
            }
        }
        base += __popc(mask);
    }
    if (lane == 0) g_deg[row] = (base < CAP) ? base : CAP;
}

// ---------------------------------------------------------------------------
// h = x @ W_in + b_in      (4096x64 @ 64x128)
// Block: 32 rows x 128 cols, thread = output column.
// ---------------------------------------------------------------------------
__global__ __launch_bounds__(128) void in_proj_kernel(
    const float* __restrict__ x, const float* __restrict__ W,
    const float* __restrict__ b)
{
    __shared__ float sx[32 * 64];
    int c  = threadIdx.x;
    int r0 = blockIdx.x * 32;
    for (int i = threadIdx.x; i < 32 * 64; i += 128)
        sx[i] = x[(long)r0 * 64 + i];
    __syncthreads();

    float acc[32];
#pragma unroll
    for (int r = 0; r < 32; r++) acc[r] = 0.0f;

    for (int k = 0; k < 64; k += 4) {
        float w0 = W[(k + 0) * HH + c];
        float w1 = W[(k + 1) * HH + c];
        float w2 = W[(k + 2) * HH + c];
        float w3 = W[(k + 3) * HH + c];
#pragma unroll
        for (int r = 0; r < 32; r++) {
            float4 xv = *(const float4*)&sx[r * 64 + k];
            acc[r] = fmaf(xv.x, w0, fmaf(xv.y, w1, fmaf(xv.z, w2, fmaf(xv.w, w3, acc[r]))));
        }
    }
    float bias = b[c];
#pragma unroll
    for (int r = 0; r < 32; r++)
        g_h[(long)(r0 + r) * HH + c] = acc[r] + bias;
}

// ---------------------------------------------------------------------------
// m_i = sum_{j in N(i)} (decay_ij * relu(<h_i, h_j>) + wc_ij) * h_j
// One block (4 warps) per row; warps stride edges; lane owns 4 hidden dims.
// ---------------------------------------------------------------------------
__global__ __launch_bounds__(128) void msg_kernel()
{
    __shared__ float s_hi[HH];
    __shared__ float s_m[4 * HH];
    int row  = blockIdx.x;
    int tid  = threadIdx.x;
    int wid  = tid >> 5;
    int lane = tid & 31;

    s_hi[tid] = g_h[(long)row * HH + tid];
    __syncthreads();
    float4 hi4 = *(const float4*)&s_hi[lane * 4];

    int deg = g_deg[row];
    float4 acc = make_float4(0.f, 0.f, 0.f, 0.f);

    for (int e = wid; e < deg; e += 4) {
        float4 em = g_edge[row * CAP + e];
        int j = __float_as_int(em.x);
        float4 hj = *(const float4*)&g_h[(long)j * HH + lane * 4];
        float dot = hi4.x * hj.x + hi4.y * hj.y + hi4.z * hj.z + hi4.w * hj.w;
#pragma unroll
        for (int o = 16; o > 0; o >>= 1)
            dot += __shfl_xor_sync(0xffffffffu, dot, o);
        float coef = fmaf(em.y, fmaxf(dot, 0.0f), em.z);
        acc.x = fmaf(coef, hj.x, acc.x);
        acc.y = fmaf(coef, hj.y, acc.y);
        acc.z = fmaf(coef, hj.z, acc.z);
        acc.w = fmaf(coef, hj.w, acc.w);
    }
    *(float4*)&s_m[wid * HH + lane * 4] = acc;
    __syncthreads();
    g_m[(long)row * HH + tid] =
        s_m[tid] + s_m[HH + tid] + s_m[2 * HH + tid] + s_m[3 * HH + tid];
}

// ---------------------------------------------------------------------------
// t = relu([h | m] @ W_u1 + b_u1)     (4096x256 @ 256x128)
// Block: 32 rows x 128 cols.
// ---------------------------------------------------------------------------
__global__ __launch_bounds__(128) void mlp1_kernel(
    const float* __restrict__ W1, const float* __restrict__ b1)
{
    __shared__ float s_cat[32 * 256];   // 32 KB
    int c  = threadIdx.x;
    int r0 = blockIdx.x * 32;
    for (int i = threadIdx.x; i < 32 * 128; i += 128) {
        int r = i >> 7, k = i & 127;
        s_cat[r * 256 + k]       = g_h[(long)(r0 + r) * HH + k];
        s_cat[r * 256 + 128 + k] = g_m[(long)(r0 + r) * HH + k];
    }
    __syncthreads();

    float acc[32];
#pragma unroll
    for (int r = 0; r < 32; r++) acc[r] = 0.0f;

    for (int k = 0; k < 256; k += 4) {
        float w0 = W1[(k + 0) * HH + c];
        float w1 = W1[(k + 1) * HH + c];
        float w2 = W1[(k + 2) * HH + c];
        float w3 = W1[(k + 3) * HH + c];
#pragma unroll
        for (int r = 0; r < 32; r++) {
            float4 cv = *(const float4*)&s_cat[r * 256 + k];
            acc[r] = fmaf(cv.x, w0, fmaf(cv.y, w1, fmaf(cv.z, w2, fmaf(cv.w, w3, acc[r]))));
        }
    }
    float bias = b1[c];
#pragma unroll
    for (int r = 0; r < 32; r++)
        g_t[(long)(r0 + r) * HH + c] = fmaxf(acc[r] + bias, 0.0f);
}

// ---------------------------------------------------------------------------
// delta = t @ W_u2 + b_u2;  y = h + delta;  out = LN(y)*gamma + beta
// Block: 32 rows x 128 cols; two-pass LN (matches reference numerics).
// ---------------------------------------------------------------------------
__global__ __launch_bounds__(128) void mlp2_ln_kernel(
    const float* __restrict__ W2, const float* __restrict__ b2,
    const float* __restrict__ gamma, const float* __restrict__ beta,
    float* __restrict__ out)
{
    __shared__ float s_t[32 * 128];   // 16 KB, reused for y
    int c  = threadIdx.x;
    int r0 = blockIdx.x * 32;
    for (int i = threadIdx.x; i < 32 * 128; i += 128)
        s_t[i] = g_t[(long)r0 * HH + i];
    __syncthreads();

    float acc[32];
#pragma unroll
    for (int r = 0; r < 32; r++) acc[r] = 0.0f;

    for (int k = 0; k < 128; k += 4) {
        float w0 = W2[(k + 0) * HH + c];
        float w1 = W2[(k + 1) * HH + c];
        float w2 = W2[(k + 2) * HH + c];
        float w3 = W2[(k + 3) * HH + c];
#pragma unroll
        for (int r = 0; r < 32; r++) {
            float4 tv = *(const float4*)&s_t[r * 128 + k];
            acc[r] = fmaf(tv.x, w0, fmaf(tv.y, w1, fmaf(tv.z, w2, fmaf(tv.w, w3, acc[r]))));
        }
    }
    float bias = b2[c];
    __syncthreads();   // done reading t; reuse smem for y
#pragma unroll
    for (int r = 0; r < 32; r++)
        s_t[r * 128 + c] = g_h[(long)(r0 + r) * HH + c] + acc[r] + bias;
    __syncthreads();

    // Layernorm: warp wid handles rows [wid*8, wid*8+8), lane owns 4 cols
    int wid  = c >> 5;
    int lane = c & 31;
    float4 gm = *(const float4*)&gamma[lane * 4];
    float4 bt = *(const float4*)&beta[lane * 4];
#pragma unroll
    for (int rr = 0; rr < 8; rr++) {
        int r = wid * 8 + rr;
        float4 yv = *(const float4*)&s_t[r * 128 + lane * 4];
        float s = yv.x + yv.y + yv.z + yv.w;
#pragma unroll
        for (int o = 16; o > 0; o >>= 1)
            s += __shfl_xor_sync(0xffffffffu, s, o);
        float mu = s * (1.0f / 128.0f);
        float dx = yv.x - mu, dy = yv.y - mu, dz = yv.z - mu, dw = yv.w - mu;
        float sq = dx * dx + dy * dy + dz * dz + dw * dw;
#pragma unroll
        for (int o = 16; o > 0; o >>= 1)
            sq += __shfl_xor_sync(0xffffffffu, sq, o);
        float rs = rsqrtf(sq * (1.0f / 128.0f) + 1e-5f);
        float4 o4;
        o4.x = dx * rs * gm.x + bt.x;
        o4.y = dy * rs * gm.y + bt.y;
        o4.z = dz * rs * gm.z + bt.z;
        o4.w = dw * rs * gm.w + bt.w;
        *(float4*)&out[(long)(r0 + r) * HH + lane * 4] = o4;
    }
}

// ---------------------------------------------------------------------------
extern "C" void kernel_launch(void* const* d_in, const int* in_sizes, int n_in,
                              void* d_out, int out_size)
{
    const float* x     = (const float*)d_in[0];
    const float* adj   = (const float*)d_in[1];
    const float* dist  = (const float*)d_in[2];
    const float* W_in  = (const float*)d_in[3];
    const float* b_in  = (const float*)d_in[4];
    // d_in[5] = W_msg, d_in[6] = b_msg : dead code in the reference
    const float* W_u1  = (const float*)d_in[7];
    const float* b_u1  = (const float*)d_in[8];
    const float* W_u2  = (const float*)d_in[9];
    const float* b_u2  = (const float*)d_in[10];
    const float* gamma = (const float*)d_in[11];
    const float* beta  = (const float*)d_in[12];
    float* out = (float*)d_out;

    float* h_ptr = nullptr;
    cudaGetSymbolAddress((void**)&h_ptr, g_h);

    build_edges_kernel<<<NN / 8, 256>>>(adj, dist);
    in_proj_kernel<<<NN / 32, 128>>>(x, W_in, b_in);
    for (int s = 0; s < 3; s++) {
        msg_kernel<<<NN, 128>>>();
        mlp1_kernel<<<NN / 32, 128>>>(W_u1, b_u1);
        mlp2_ln_kernel<<<NN / 32, 128>>>(W_u2, b_u2, gamma, beta,
                                         (s == 2) ? out : h_ptr);
    }
}

// round 2
// speedup vs baseline: 1.4219x; 1.4219x over previous
#include <cuda_runtime.h>

#define NN   4096
#define HH   128
#define CAP  192   // max degree capacity; Binomial(4096,0.02) max ~= 120

// Scratch (device globals: allocation-free per harness rules)
__device__ float4 g_edge[NN * CAP];   // (j_bits, decay, wc, pad) per edge
__device__ int    g_deg[NN];
__device__ float  g_h[NN * HH];
__device__ float  g_m[NN * HH];

// ---------------------------------------------------------------------------
// Build per-row edge list from adj (2% dense) with loop-invariant weights.
// One warp per row; 4-way load batching for MLP=4 on the adj scan.
// Ordered ballot compaction (deterministic).
// ---------------------------------------------------------------------------
__global__ __launch_bounds__(256) void build_edges_kernel(
    const float* __restrict__ adj, const float* __restrict__ dist)
{
    int row  = blockIdx.x * 8 + (threadIdx.x >> 5);
    int lane = threadIdx.x & 31;
    if (row >= NN) return;
    const float* arow = adj  + (long)row * NN;
    const float* drow = dist + (long)row * NN;
    unsigned lt = (1u << lane) - 1u;
    int base = 0;
    for (int c0 = 0; c0 < NN; c0 += 128) {
        // batch 4 loads before any ballot -> MLP=4
        float a0 = arow[c0 + lane];
        float a1 = arow[c0 + 32 + lane];
        float a2 = arow[c0 + 64 + lane];
        float a3 = arow[c0 + 96 + lane];
        unsigned m0 = __ballot_sync(0xffffffffu, a0 != 0.0f);
        unsigned m1 = __ballot_sync(0xffffffffu, a1 != 0.0f);
        unsigned m2 = __ballot_sync(0xffffffffu, a2 != 0.0f);
        unsigned m3 = __ballot_sync(0xffffffffu, a3 != 0.0f);
#pragma unroll
        for (int q = 0; q < 4; q++) {
            float    a    = (q == 0) ? a0 : (q == 1) ? a1 : (q == 2) ? a2 : a3;
            unsigned mask = (q == 0) ? m0 : (q == 1) ? m1 : (q == 2) ? m2 : m3;
            int      col  = c0 + q * 32 + lane;
            if (a != 0.0f) {
                int pos = base + __popc(mask & lt);
                if (pos < CAP) {
                    float d     = drow[col];
                    float decay = __expf(d * (-1.0f / 3.0f));
                    float r     = fmaxf(d, 1e-6f);
                    float inv   = 3.5f / r;
                    float i2    = inv * inv;
                    float i6    = i2 * i2 * i2;
                    float wc    = 0.04f * (i6 * i6 - i6);
                    g_edge[row * CAP + pos] =
                        make_float4(__int_as_float(col), decay, wc, 0.0f);
                }
            }
            base += __popc(mask);
        }
    }
    if (lane == 0) g_deg[row] = (base < CAP) ? base : CAP;
}

// ---------------------------------------------------------------------------
// h = x @ W_in + b_in      (4096x64 @ 64x128); 8 rows/block, grid 512
// ---------------------------------------------------------------------------
__global__ __launch_bounds__(128) void in_proj_kernel(
    const float* __restrict__ x, const float* __restrict__ W,
    const float* __restrict__ b)
{
    __shared__ float sx[8 * 64];
    int c  = threadIdx.x;
    int r0 = blockIdx.x * 8;
    for (int i = threadIdx.x; i < 8 * 64; i += 128)
        sx[i] = x[(long)r0 * 64 + i];
    __syncthreads();

    float acc[8];
#pragma unroll
    for (int r = 0; r < 8; r++) acc[r] = 0.0f;

#pragma unroll 4
    for (int k = 0; k < 64; k += 4) {
        float w0 = W[(k + 0) * HH + c];
        float w1 = W[(k + 1) * HH + c];
        float w2 = W[(k + 2) * HH + c];
        float w3 = W[(k + 3) * HH + c];
#pragma unroll
        for (int r = 0; r < 8; r++) {
            float4 xv = *(const float4*)&sx[r * 64 + k];
            acc[r] = fmaf(xv.x, w0, fmaf(xv.y, w1, fmaf(xv.z, w2, fmaf(xv.w, w3, acc[r]))));
        }
    }
    float bias = b[c];
#pragma unroll
    for (int r = 0; r < 8; r++)
        g_h[(long)(r0 + r) * HH + c] = acc[r] + bias;
}

// ---------------------------------------------------------------------------
// m_i = sum_{j in N(i)} (decay_ij * relu(<h_i, h_j>) + wc_ij) * h_j
// One block (4 warps) per row; warps take edge PAIRS (stride 8) so the two
// shfl-reduce chains interleave. Lane owns 4 hidden dims.
// ---------------------------------------------------------------------------
__global__ __launch_bounds__(128) void msg_kernel()
{
    __shared__ float s_hi[HH];
    __shared__ float s_m[4 * HH];
    int row  = blockIdx.x;
    int tid  = threadIdx.x;
    int wid  = tid >> 5;
    int lane = tid & 31;

    s_hi[tid] = g_h[(long)row * HH + tid];
    __syncthreads();
    float4 hi4 = *(const float4*)&s_hi[lane * 4];

    int deg = g_deg[row];
    const float4* ebase = &g_edge[row * CAP];
    float4 acc = make_float4(0.f, 0.f, 0.f, 0.f);

    int e = wid * 2;
    for (; e + 1 < deg; e += 8) {
        float4 em0 = ebase[e];
        float4 em1 = ebase[e + 1];
        int j0 = __float_as_int(em0.x);
        int j1 = __float_as_int(em1.x);
        float4 hj0 = *(const float4*)&g_h[(long)j0 * HH + lane * 4];
        float4 hj1 = *(const float4*)&g_h[(long)j1 * HH + lane * 4];
        float d0 = hi4.x * hj0.x + hi4.y * hj0.y + hi4.z * hj0.z + hi4.w * hj0.w;
        float d1 = hi4.x * hj1.x + hi4.y * hj1.y + hi4.z * hj1.z + hi4.w * hj1.w;
#pragma unroll
        for (int o = 16; o > 0; o >>= 1) {
            d0 += __shfl_xor_sync(0xffffffffu, d0, o);
            d1 += __shfl_xor_sync(0xffffffffu, d1, o);
        }
        float c0 = fmaf(em0.y, fmaxf(d0, 0.0f), em0.z);
        float c1 = fmaf(em1.y, fmaxf(d1, 0.0f), em1.z);
        acc.x = fmaf(c1, hj1.x, fmaf(c0, hj0.x, acc.x));
        acc.y = fmaf(c1, hj1.y, fmaf(c0, hj0.y, acc.y));
        acc.z = fmaf(c1, hj1.z, fmaf(c0, hj0.z, acc.z));
        acc.w = fmaf(c1, hj1.w, fmaf(c0, hj0.w, acc.w));
    }
    if (e < deg) {   // odd tail edge owned by this warp
        float4 em = ebase[e];
        int j = __float_as_int(em.x);
        float4 hj = *(const float4*)&g_h[(long)j * HH + lane * 4];
        float dot = hi4.x * hj.x + hi4.y * hj.y + hi4.z * hj.z + hi4.w * hj.w;
#pragma unroll
        for (int o = 16; o > 0; o >>= 1)
            dot += __shfl_xor_sync(0xffffffffu, dot, o);
        float cf = fmaf(em.y, fmaxf(dot, 0.0f), em.z);
        acc.x = fmaf(cf, hj.x, acc.x);
        acc.y = fmaf(cf, hj.y, acc.y);
        acc.z = fmaf(cf, hj.z, acc.z);
        acc.w = fmaf(cf, hj.w, acc.w);
    }
    *(float4*)&s_m[wid * HH + lane * 4] = acc;
    __syncthreads();
    g_m[(long)row * HH + tid] =
        s_m[tid] + s_m[HH + tid] + s_m[2 * HH + tid] + s_m[3 * HH + tid];
}

// ---------------------------------------------------------------------------
// Fused update: t = relu([h|m]@W1+b1); delta = t@W2+b2; out = LN(h+delta)
// 8 rows/block -> grid 512. All intermediates stay in smem.
// ---------------------------------------------------------------------------
__global__ __launch_bounds__(128) void update_kernel(
    const float* __restrict__ W1, const float* __restrict__ b1,
    const float* __restrict__ W2, const float* __restrict__ b2,
    const float* __restrict__ gamma, const float* __restrict__ beta,
    float* __restrict__ out)
{
    __shared__ float s_cat[8 * 256];   // [r][0:128)=h, [r][128:256)=m, later y
    __shared__ float s_t[8 * 128];
    int c  = threadIdx.x;
    int r0 = blockIdx.x * 8;

    for (int i = threadIdx.x; i < 8 * 128; i += 128) {
        int r = i >> 7, k = i & 127;
        s_cat[r * 256 + k]       = g_h[(long)(r0 + r) * HH + k];
        s_cat[r * 256 + 128 + k] = g_m[(long)(r0 + r) * HH + k];
    }
    __syncthreads();

    // ---- mlp1: t = relu(cat @ W1 + b1) ----
    float acc[8];
#pragma unroll
    for (int r = 0; r < 8; r++) acc[r] = 0.0f;
#pragma unroll 4
    for (int k = 0; k < 256; k += 4) {
        float w0 = W1[(k + 0) * HH + c];
        float w1 = W1[(k + 1) * HH + c];
        float w2 = W1[(k + 2) * HH + c];
        float w3 = W1[(k + 3) * HH + c];
#pragma unroll
        for (int r = 0; r < 8; r++) {
            float4 cv = *(const float4*)&s_cat[r * 256 + k];
            acc[r] = fmaf(cv.x, w0, fmaf(cv.y, w1, fmaf(cv.z, w2, fmaf(cv.w, w3, acc[r]))));
        }
    }
    {
        float bias = b1[c];
#pragma unroll
        for (int r = 0; r < 8; r++)
            s_t[r * 128 + c] = fmaxf(acc[r] + bias, 0.0f);
    }
    __syncthreads();

    // ---- mlp2: delta = t @ W2 + b2 ----
#pragma unroll
    for (int r = 0; r < 8; r++) acc[r] = 0.0f;
#pragma unroll 4
    for (int k = 0; k < 128; k += 4) {
        float w0 = W2[(k + 0) * HH + c];
        float w1 = W2[(k + 1) * HH + c];
        float w2 = W2[(k + 2) * HH + c];
        float w3 = W2[(k + 3) * HH + c];
#pragma unroll
        for (int r = 0; r < 8; r++) {
            float4 tv = *(const float4*)&s_t[r * 128 + k];
            acc[r] = fmaf(tv.x, w0, fmaf(tv.y, w1, fmaf(tv.z, w2, fmaf(tv.w, w3, acc[r]))));
        }
    }
    // y = h + delta + b2 -> overwrite m-region (all m reads finished pre-sync)
    {
        float bias = b2[c];
#pragma unroll
        for (int r = 0; r < 8; r++)
            s_cat[r * 256 + 128 + c] = s_cat[r * 256 + c] + acc[r] + bias;
    }
    __syncthreads();

    // ---- layernorm: warp wid handles rows [wid*2, wid*2+2), lane owns 4 cols
    int wid  = c >> 5;
    int lane = c & 31;
    float4 gm = *(const float4*)&gamma[lane * 4];
    float4 bt = *(const float4*)&beta[lane * 4];
#pragma unroll
    for (int rr = 0; rr < 2; rr++) {
        int r = wid * 2 + rr;
        float4 yv = *(const float4*)&s_cat[r * 256 + 128 + lane * 4];
        float s = yv.x + yv.y + yv.z + yv.w;
#pragma unroll
        for (int o = 16; o > 0; o >>= 1)
            s += __shfl_xor_sync(0xffffffffu, s, o);
        float mu = s * (1.0f / 128.0f);
        float dx = yv.x - mu, dy = yv.y - mu, dz = yv.z - mu, dw = yv.w - mu;
        float sq = dx * dx + dy * dy + dz * dz + dw * dw;
#pragma unroll
        for (int o = 16; o > 0; o >>= 1)
            sq += __shfl_xor_sync(0xffffffffu, sq, o);
        float rs = rsqrtf(sq * (1.0f / 128.0f) + 1e-5f);
        float4 o4;
        o4.x = dx * rs * gm.x + bt.x;
        o4.y = dy * rs * gm.y + bt.y;
        o4.z = dz * rs * gm.z + bt.z;
        o4.w = dw * rs * gm.w + bt.w;
        *(float4*)&out[(long)(r0 + r) * HH + lane * 4] = o4;
    }
}

// ---------------------------------------------------------------------------
extern "C" void kernel_launch(void* const* d_in, const int* in_sizes, int n_in,
                              void* d_out, int out_size)
{
    const float* x     = (const float*)d_in[0];
    const float* adj   = (const float*)d_in[1];
    const float* dist  = (const float*)d_in[2];
    const float* W_in  = (const float*)d_in[3];
    const float* b_in  = (const float*)d_in[4];
    // d_in[5] = W_msg, d_in[6] = b_msg : dead code in the reference
    const float* W_u1  = (const float*)d_in[7];
    const float* b_u1  = (const float*)d_in[8];
    const float* W_u2  = (const float*)d_in[9];
    const float* b_u2  = (const float*)d_in[10];
    const float* gamma = (const float*)d_in[11];
    const float* beta  = (const float*)d_in[12];
    float* out = (float*)d_out;

    float* h_ptr = nullptr;
    cudaGetSymbolAddress((void**)&h_ptr, g_h);

    build_edges_kernel<<<NN / 8, 256>>>(adj, dist);
    in_proj_kernel<<<NN / 8, 128>>>(x, W_in, b_in);
    for (int s = 0; s < 3; s++) {
        msg_kernel<<<NN, 128>>>();
        update_kernel<<<NN / 8, 128>>>(W_u1, b_u1, W_u2, b_u2, gamma, beta,
                                       (s == 2) ? out : h_ptr);
    }
}